// round 12
// baseline (speedup 1.0000x reference)
#include <cuda_runtime.h>
#include <cuda_bf16.h>
#include <cstdint>

#define NN 6400
#define CC 64
#define CP 128          // augmented K: [hi | lo] bf16
#define HH 80
#define NSPLIT 5        // column splits; grid = 5 x 50 = 250 CTAs, 10 tiles each
#define NTILES 50
#define LTILES 10       // tiles per CTA
#define TILE_BYTES 32768
#define SQRT_LOG2E 1.2011224087864498f

// dynamic smem: sA (32KB) + sB0 (32KB) + sB1 (32KB)
#define SB0_OFF 32768
#define SB1_OFF 65536
#define SMEM_BYTES 98304

// augmented bf16 operand matrix P = [bf16(x') | bf16(x' - bf16(x'))] with
// x' = x * sqrt(log2 e)  (logits come out in log2 domain -> ex2 not exp).
// stored PRE-SWIZZLED: 16B chunk c of row r lives at chunk (c ^ (r&7)).
__device__ __nv_bfloat16 g_P[(size_t)NN * CP];
__device__ float g_MS[NSPLIT][NN];    // per-(split,row) partial sum of ex2
__device__ float g_M[NN];             // per-row shift = ||x'||^2 (log2-domain)
__device__ float g_Z[NN];
__device__ float d_E[HH];             // exp(-d^2/2)
__device__ float d_S1[HH];            // sum_r E[|t-r|]

// ---------------------------------------------------------------------------
__device__ __forceinline__ float ex2f(float x) {
    float r; asm("ex2.approx.f32 %0, %1;" : "=f"(r) : "f"(x)); return r;
}

__device__ __forceinline__ void mma16816(float* c, const uint32_t* a,
                                         const uint32_t* b) {
    asm volatile(
        "mma.sync.aligned.m16n8k16.row.col.f32.bf16.bf16.f32 "
        "{%0,%1,%2,%3}, {%4,%5,%6,%7}, {%8,%9}, {%0,%1,%2,%3};"
        : "+f"(c[0]), "+f"(c[1]), "+f"(c[2]), "+f"(c[3])
        : "r"(a[0]), "r"(a[1]), "r"(a[2]), "r"(a[3]),
          "r"(b[0]), "r"(b[1]));
}

__device__ __forceinline__ void ldsm4(uint32_t* r, uint32_t addr) {
    asm volatile(
        "ldmatrix.sync.aligned.m8n8.x4.shared.b16 {%0,%1,%2,%3}, [%4];"
        : "=r"(r[0]), "=r"(r[1]), "=r"(r[2]), "=r"(r[3]) : "r"(addr));
}

__device__ __forceinline__ void mbar_init(uint32_t a, uint32_t cnt) {
    asm volatile("mbarrier.init.shared.b64 [%0], %1;" :: "r"(a), "r"(cnt) : "memory");
}
__device__ __forceinline__ void mbar_expect(uint32_t a, uint32_t bytes) {
    asm volatile("mbarrier.arrive.expect_tx.shared.b64 _, [%0], %1;"
                 :: "r"(a), "r"(bytes) : "memory");
}
__device__ __forceinline__ void mbar_wait(uint32_t a) {
    uint32_t done = 0;
    while (!done)
        asm volatile(
            "{ .reg .pred p; mbarrier.try_wait.parity.shared::cta.b64 p, [%1], %2;"
            " selp.b32 %0, 1, 0, p; }"
            : "=r"(done) : "r"(a), "r"(0) : "memory");
}
// one-instruction 32KB tile copy: global (contiguous, pre-swizzled) -> smem
__device__ __forceinline__ void bulk_g2s(uint32_t dst, const void* src,
                                         uint32_t bytes, uint32_t mbar) {
    asm volatile(
        "cp.async.bulk.shared::cta.global.mbarrier::complete_tx::bytes "
        "[%0], [%1], %2, [%3];"
        :: "r"(dst), "l"(src), "r"(bytes), "r"(mbar) : "memory");
}

// full-K (8 t-steps) mma over resident sA + one sB buffer (swizzled layout)
__device__ __forceinline__ void mma_tile(float acc[2][8][4],
                                         uint32_t abase0, uint32_t abase1,
                                         const uint32_t* bbase, uint32_t bbuf,
                                         int c0a, int c0b, int lr) {
    #pragma unroll
    for (int t = 0; t < 8; t++) {
        uint32_t ca = (uint32_t)((((t << 1) | c0a) ^ lr) << 4);
        uint32_t cb = (uint32_t)((((t << 1) | c0b) ^ lr) << 4);
        uint32_t afr[2][4];
        ldsm4(afr[0], abase0 + ca);
        ldsm4(afr[1], abase1 + ca);
        uint32_t bf[16];
        #pragma unroll
        for (int q = 0; q < 4; q++)
            ldsm4(&bf[q * 4], bbuf + bbase[q] + cb);
        #pragma unroll
        for (int mt = 0; mt < 2; mt++)
            #pragma unroll
            for (int nt = 0; nt < 8; nt++)
                mma16816(acc[mt][nt], afr[mt], &bf[nt * 2]);
    }
}

// ---------------------------------------------------------------------------
// kprep: build P pre-swizzled + scaled; compute g_M = ||x'||^2 per row;
// block 0 also builds Ad tables (E, S1).
// ---------------------------------------------------------------------------
__global__ __launch_bounds__(256) void kprep(const float* __restrict__ X) {
    int t = blockIdx.x * 256 + threadIdx.x;
    int row = t >> 3;
    int c   = t & 7;
    const float4* src = reinterpret_cast<const float4*>(
        X + (size_t)row * CC + c * 8);
    float4 v0 = src[0];
    float4 v1 = src[1];

    float xs[8] = {v0.x, v0.y, v0.z, v0.w, v1.x, v1.y, v1.z, v1.w};
    __nv_bfloat16 h[8], l[8];
    float nrm = 0.0f;
    #pragma unroll
    for (int i = 0; i < 8; i++) {
        float x = xs[i] * SQRT_LOG2E;
        nrm += x * x;
        __nv_bfloat16 hh = __float2bfloat16_rn(x);
        h[i] = hh;
        l[i] = __float2bfloat16_rn(x - __bfloat162float(hh));
    }
    // row-norm reduce across the 8 lanes of this row
    nrm += __shfl_xor_sync(0xFFFFFFFFu, nrm, 1);
    nrm += __shfl_xor_sync(0xFFFFFFFFu, nrm, 2);
    nrm += __shfl_xor_sync(0xFFFFFFFFu, nrm, 4);
    if (c == 0) g_M[row] = nrm;

    uint32_t off = (uint32_t)row * 256 + (uint32_t)((c ^ (row & 7)) * 16);
    char* base = reinterpret_cast<char*>(g_P);
    *reinterpret_cast<uint4*>(base + off)       = *reinterpret_cast<uint4*>(h);
    *reinterpret_cast<uint4*>(base + off + 128) = *reinterpret_cast<uint4*>(l);

    if (blockIdx.x == 0 && threadIdx.x < HH) {
        int tt = threadIdx.x;
        d_E[tt] = __expf(-0.5f * (float)(tt * tt));
        float s = 0.0f;
        #pragma unroll 8
        for (int r = 0; r < HH; r++) {
            int d = tt - r;
            s += __expf(-0.5f * (float)(d * d));
        }
        d_S1[tt] = s;
    }
}

// ---------------------------------------------------------------------------
// kA: pass A — sA-resident GEMM over 10 column tiles (bulk-copy pipelined),
// per-row partial sums of ex2(v - m), PLUS fused analytic Ad tile stores
// (table-driven, overlapping the tensor mainloop's idle DRAM/issue slots).
// ---------------------------------------------------------------------------
__global__ __launch_bounds__(256, 2) void kA(float* __restrict__ Ad) {
    extern __shared__ __nv_bfloat16 smem[];
    __shared__ float sZ[2][128];
    __shared__ float sE[HH];
    __shared__ alignas(8) uint64_t mbar_s[LTILES + 1];

    const int tid  = threadIdx.x;
    const int lane = tid & 31;
    const int wid  = tid >> 5;
    const int warpM = wid & 3;
    const int warpN = wid >> 2;
    const int g  = lane >> 2;
    const int lr = lane & 7;
    const int r0 = blockIdx.y * 128;
    const int split = blockIdx.x;

    uint32_t s_u = (uint32_t)__cvta_generic_to_shared(smem);
    const uint32_t sa_b = s_u;
    const uint32_t sb_b[2] = { s_u + SB0_OFF, s_u + SB1_OFF };
    uint32_t mb_u = (uint32_t)__cvta_generic_to_shared(mbar_s);

    // LDSM lane row-bases (swizzled layout: row stride 256B)
    const int c0a = lane >> 4;
    const int c0b = (lane >> 3) & 1;
    uint32_t abase0, abase1, bbase[4];
    {
        int rA0 = warpM * 32 + 0  + ((lane >> 3) & 1) * 8 + lr;
        int rA1 = warpM * 32 + 16 + ((lane >> 3) & 1) * 8 + lr;
        abase0 = sa_b + rA0 * 256;
        abase1 = sa_b + rA1 * 256;
        #pragma unroll
        for (int q = 0; q < 4; q++) {
            int n = warpN * 64 + (q * 2 + (lane >> 4)) * 8 + lr;
            bbase[q] = (uint32_t)(n * 256);
        }
    }

    // per-slot fixed shift
    float pm[4];
    #pragma unroll
    for (int s = 0; s < 4; s++) {
        int row = r0 + warpM * 32 + (s >> 1) * 16 + (s & 1) * 8 + g;
        pm[s] = g_M[row];
    }

    if (tid < HH) sE[tid] = __ldg(&d_E[tid]);
    if (tid == 0) {
        #pragma unroll
        for (int i = 0; i <= LTILES; i++) mbar_init(mb_u + i * 8, 1);
    }
    __syncthreads();

    // per-thread Ad row constants (row fixed for whole CTA)
    const int ad_i   = r0 + (tid >> 1);
    const int ad_ri  = ad_i / HH;
    const int ad_ci  = ad_i - ad_ri * HH;
    const float ad_inv = 1.0f / (__ldg(&d_S1[ad_ri]) * __ldg(&d_S1[ad_ci]) - 1.0f);
    const int ad_half = (tid & 1) * 64;

    const char* gp = reinterpret_cast<const char*>(g_P);
    if (tid == 0) {
        mbar_expect(mb_u, TILE_BYTES);
        bulk_g2s(sa_b, gp + (size_t)r0 * 256, TILE_BYTES, mb_u);
        mbar_expect(mb_u + 8, TILE_BYTES);
        bulk_g2s(sb_b[0], gp + (size_t)(split * 128) * 256, TILE_BYTES, mb_u + 8);
        mbar_expect(mb_u + 16, TILE_BYTES);
        bulk_g2s(sb_b[1], gp + (size_t)((split + NSPLIT) * 128) * 256, TILE_BYTES, mb_u + 16);
    }
    mbar_wait(mb_u);   // sA ready

    float s_run[4] = {0.0f, 0.0f, 0.0f, 0.0f};

    #pragma unroll 1
    for (int li = 0; li < LTILES; li++) {
        const int c0 = (split + li * NSPLIT) * 128;
        mbar_wait(mb_u + (li + 1) * 8);

        float acc[2][8][4];
        #pragma unroll
        for (int mt = 0; mt < 2; mt++)
            #pragma unroll
            for (int nt = 0; nt < 8; nt++)
                #pragma unroll
                for (int i = 0; i < 4; i++)
                    acc[mt][nt][i] = 0.0f;

        mma_tile(acc, abase0, abase1, bbase, sb_b[li & 1], c0a, c0b, lr);

        __syncthreads();   // all warps done with sb_b[li&1]
        if (tid == 0 && li + 2 < LTILES) {
            int ct = split + (li + 2) * NSPLIT;
            mbar_expect(mb_u + (li + 3) * 8, TILE_BYTES);
            bulk_g2s(sb_b[li & 1], gp + (size_t)(ct * 128) * 256, TILE_BYTES,
                     mb_u + (li + 3) * 8);
        }

        // fused analytic Ad stores for tile (r0..+127, c0..+127)
        {
            int j0 = c0 + ad_half;
            int rj = j0 / HH;
            int cj = j0 - rj * HH;
            float* dst = Ad + (size_t)ad_i * NN + j0;
            #pragma unroll
            for (int it = 0; it < 16; it++) {
                int dr = ad_ri - rj; dr = dr < 0 ? -dr : dr;
                float er = sE[dr] * ad_inv;
                int d0 = ad_ci - cj;     d0 = d0 < 0 ? -d0 : d0;
                int d1 = ad_ci - cj - 1; d1 = d1 < 0 ? -d1 : d1;
                int d2 = ad_ci - cj - 2; d2 = d2 < 0 ? -d2 : d2;
                int d3 = ad_ci - cj - 3; d3 = d3 < 0 ? -d3 : d3;
                float4 o;
                o.x = er * sE[d0];
                o.y = er * sE[d1];
                o.z = er * sE[d2];
                o.w = er * sE[d3];
                if (rj == ad_ri) {
                    int dc = ad_ci - cj;
                    if (dc == 0) o.x = 0.0f;
                    if (dc == 1) o.y = 0.0f;
                    if (dc == 2) o.z = 0.0f;
                    if (dc == 3) o.w = 0.0f;
                }
                __stcs(reinterpret_cast<float4*>(dst), o);
                dst += 4;
                cj += 4;
                if (cj >= HH) { cj -= HH; rj++; }
            }
        }

        // fixed-shift partial sums (overlaps next tile's bulk copy)
        #pragma unroll
        for (int s = 0; s < 4; s++) {
            const int mt = s >> 1, h2 = (s & 1) * 2;
            float ssum = 0.0f;
            #pragma unroll
            for (int nt = 0; nt < 8; nt++)
                ssum += ex2f(acc[mt][nt][h2] - pm[s]) +
                        ex2f(acc[mt][nt][h2 + 1] - pm[s]);
            s_run[s] += ssum;
        }
    }

    // sum across the 4 lanes of each quad (same g -> same rows)
    #pragma unroll
    for (int s = 0; s < 4; s++) {
        s_run[s] += __shfl_xor_sync(0xFFFFFFFFu, s_run[s], 1);
        s_run[s] += __shfl_xor_sync(0xFFFFFFFFu, s_run[s], 2);
    }
    if ((lane & 3) == 0) {
        #pragma unroll
        for (int s = 0; s < 4; s++) {
            int rl = warpM * 32 + (s >> 1) * 16 + (s & 1) * 8 + g;
            sZ[warpN][rl] = s_run[s];
        }
    }
    __syncthreads();
    if (tid < 128)
        g_MS[split][r0 + tid] = sZ[0][tid] + sZ[1][tid];
}

// ---------------------------------------------------------------------------
// kms: merge the NSPLIT partial sums -> g_Z
// ---------------------------------------------------------------------------
__global__ __launch_bounds__(256) void kms() {
    int r = blockIdx.x * 256 + threadIdx.x;   // 25 blocks
    float S = 0.0f;
    #pragma unroll
    for (int i = 0; i < NSPLIT; i++) S += g_MS[i][r];
    g_Z[r] = S;
}

// ---------------------------------------------------------------------------
// kB: pass B — same pipelined GEMM, fused softmax finalize + threshold,
// streaming stores.
// ---------------------------------------------------------------------------
__global__ __launch_bounds__(256, 2) void kB(float* __restrict__ As) {
    extern __shared__ __nv_bfloat16 smem[];
    __shared__ alignas(8) uint64_t mbar_s[LTILES + 1];

    const int tid  = threadIdx.x;
    const int lane = tid & 31;
    const int wid  = tid >> 5;
    const int warpM = wid & 3;
    const int warpN = wid >> 2;
    const int g  = lane >> 2;
    const int tg = lane & 3;
    const int lr = lane & 7;
    const int r0 = blockIdx.y * 128;
    const int split = blockIdx.x;

    uint32_t s_u = (uint32_t)__cvta_generic_to_shared(smem);
    const uint32_t sa_b = s_u;
    const uint32_t sb_b[2] = { s_u + SB0_OFF, s_u + SB1_OFF };
    uint32_t mb_u = (uint32_t)__cvta_generic_to_shared(mbar_s);

    const int c0a = lane >> 4;
    const int c0b = (lane >> 3) & 1;
    uint32_t abase0, abase1, bbase[4];
    {
        int rA0 = warpM * 32 + 0  + ((lane >> 3) & 1) * 8 + lr;
        int rA1 = warpM * 32 + 16 + ((lane >> 3) & 1) * 8 + lr;
        abase0 = sa_b + rA0 * 256;
        abase1 = sa_b + rA1 * 256;
        #pragma unroll
        for (int q = 0; q < 4; q++) {
            int n = warpN * 64 + (q * 2 + (lane >> 4)) * 8 + lr;
            bbase[q] = (uint32_t)(n * 256);
        }
    }

    if (tid == 0) {
        #pragma unroll
        for (int i = 0; i <= LTILES; i++) mbar_init(mb_u + i * 8, 1);
    }
    __syncthreads();

    const char* gp = reinterpret_cast<const char*>(g_P);
    if (tid == 0) {
        mbar_expect(mb_u, TILE_BYTES);
        bulk_g2s(sa_b, gp + (size_t)r0 * 256, TILE_BYTES, mb_u);
        mbar_expect(mb_u + 8, TILE_BYTES);
        bulk_g2s(sb_b[0], gp + (size_t)(split * 128) * 256, TILE_BYTES, mb_u + 8);
        mbar_expect(mb_u + 16, TILE_BYTES);
        bulk_g2s(sb_b[1], gp + (size_t)((split + NSPLIT) * 128) * 256, TILE_BYTES, mb_u + 16);
    }

    // per-slot softmax params (overlaps with bulk copies)
    float pm[4], piz[4], pth[4];
    #pragma unroll
    for (int s = 0; s < 4; s++) {
        int row = r0 + warpM * 32 + (s >> 1) * 16 + (s & 1) * 8 + g;
        float Z = g_Z[row];
        pm[s]  = g_M[row];
        piz[s] = 1.0f / Z;
        pth[s] = Z * (1.0f / (float)NN);
    }

    mbar_wait(mb_u);   // sA ready

    #pragma unroll 1
    for (int li = 0; li < LTILES; li++) {
        const int ct = split + li * NSPLIT;
        mbar_wait(mb_u + (li + 1) * 8);

        float acc[2][8][4];
        #pragma unroll
        for (int mt = 0; mt < 2; mt++)
            #pragma unroll
            for (int nt = 0; nt < 8; nt++)
                #pragma unroll
                for (int i = 0; i < 4; i++)
                    acc[mt][nt][i] = 0.0f;

        mma_tile(acc, abase0, abase1, bbase, sb_b[li & 1], c0a, c0b, lr);

        __syncthreads();   // done reading sb_b[li&1]
        if (tid == 0 && li + 2 < LTILES) {
            int ctn = split + (li + 2) * NSPLIT;
            mbar_expect(mb_u + (li + 3) * 8, TILE_BYTES);
            bulk_g2s(sb_b[li & 1], gp + (size_t)(ctn * 128) * 256, TILE_BYTES,
                     mb_u + (li + 3) * 8);
        }

        // fused softmax epilogue + streaming store for this column tile
        const int c0 = ct * 128;
        #pragma unroll
        for (int mt = 0; mt < 2; mt++) {
            const int s0 = mt * 2, s1 = mt * 2 + 1;
            #pragma unroll
            for (int nt = 0; nt < 8; nt++) {
                int row = r0 + warpM * 32 + mt * 16 + g;
                int col = c0 + warpN * 64 + nt * 8 + tg * 2;
                float e0 = ex2f(acc[mt][nt][0] - pm[s0]);
                float e1 = ex2f(acc[mt][nt][1] - pm[s0]);
                float e2 = ex2f(acc[mt][nt][2] - pm[s1]);
                float e3 = ex2f(acc[mt][nt][3] - pm[s1]);
                float2 v0, v1;
                v0.x = (e0 < pth[s0]) ? 0.0f : e0 * piz[s0];
                v0.y = (e1 < pth[s0]) ? 0.0f : e1 * piz[s0];
                v1.x = (e2 < pth[s1]) ? 0.0f : e2 * piz[s1];
                v1.y = (e3 < pth[s1]) ? 0.0f : e3 * piz[s1];
                __stcs(reinterpret_cast<float2*>(&As[(size_t)row * NN + col]), v0);
                __stcs(reinterpret_cast<float2*>(&As[(size_t)(row + 8) * NN + col]), v1);
            }
        }
    }
}

// ---------------------------------------------------------------------------
extern "C" void kernel_launch(void* const* d_in, const int* in_sizes, int n_in,
                              void* d_out, int out_size) {
    const float* X = (const float*)d_in[0];
    float* Ad = (float*)d_out;                       // first N*N floats
    float* As = (float*)d_out + (size_t)NN * NN;     // second N*N floats

    static bool attr_done = false;
    if (!attr_done) {
        cudaFuncSetAttribute(kA, cudaFuncAttributeMaxDynamicSharedMemorySize, SMEM_BYTES);
        cudaFuncSetAttribute(kB, cudaFuncAttributeMaxDynamicSharedMemorySize, SMEM_BYTES);
        attr_done = true;
    }

    kprep<<<200, 256>>>(X);
    kA<<<dim3(NSPLIT, NN / 128), 256, SMEM_BYTES>>>(Ad);
    kms<<<NN / 256, 256>>>();
    kB<<<dim3(NSPLIT, NN / 128), 256, SMEM_BYTES>>>(As);
}

// round 13
// speedup vs baseline: 1.5982x; 1.5982x over previous
#include <cuda_runtime.h>
#include <cuda_bf16.h>
#include <cstdint>

#define NN 6400
#define CC 64
#define CP 128          // augmented K: [hi | lo] bf16
#define HH 80
#define NSPLIT 25       // column splits; each CTA owns 2 adjacent tiles
#define NTILES 50
#define TILE_BYTES 32768
#define SQRT_LOG2E 1.2011224087864498f

// dynamic smem: sA (32KB) + sB0 (32KB) + sB1 (32KB); no buffer is ever reused
#define SB0_OFF 32768
#define SB1_OFF 65536
#define SMEM_BYTES 98304

// augmented bf16 operand matrix P = [bf16(x') | bf16(x' - bf16(x'))] with
// x' = x * sqrt(log2 e)  (logits come out in log2 domain -> ex2 not exp).
// stored PRE-SWIZZLED: 16B chunk c of row r lives at chunk (c ^ (r&7)).
__device__ __nv_bfloat16 g_P[(size_t)NN * CP];
__device__ float g_MS[NSPLIT][NN];    // per-(split,row) partial sum of ex2
__device__ float g_M[NN];             // per-row shift = ||x'||^2 (log2-domain)
__device__ float g_Z[NN];
__device__ float d_E[HH];             // exp(-d^2/2)
__device__ float d_S1[HH];            // sum_r E[|t-r|]

// ---------------------------------------------------------------------------
__device__ __forceinline__ float ex2f(float x) {
    float r; asm("ex2.approx.f32 %0, %1;" : "=f"(r) : "f"(x)); return r;
}

__device__ __forceinline__ void mma16816(float* c, const uint32_t* a,
                                         const uint32_t* b) {
    asm volatile(
        "mma.sync.aligned.m16n8k16.row.col.f32.bf16.bf16.f32 "
        "{%0,%1,%2,%3}, {%4,%5,%6,%7}, {%8,%9}, {%0,%1,%2,%3};"
        : "+f"(c[0]), "+f"(c[1]), "+f"(c[2]), "+f"(c[3])
        : "r"(a[0]), "r"(a[1]), "r"(a[2]), "r"(a[3]),
          "r"(b[0]), "r"(b[1]));
}

__device__ __forceinline__ void ldsm4(uint32_t* r, uint32_t addr) {
    asm volatile(
        "ldmatrix.sync.aligned.m8n8.x4.shared.b16 {%0,%1,%2,%3}, [%4];"
        : "=r"(r[0]), "=r"(r[1]), "=r"(r[2]), "=r"(r[3]) : "r"(addr));
}

__device__ __forceinline__ void mbar_init(uint32_t a, uint32_t cnt) {
    asm volatile("mbarrier.init.shared.b64 [%0], %1;" :: "r"(a), "r"(cnt) : "memory");
}
__device__ __forceinline__ void mbar_expect(uint32_t a, uint32_t bytes) {
    asm volatile("mbarrier.arrive.expect_tx.shared.b64 _, [%0], %1;"
                 :: "r"(a), "r"(bytes) : "memory");
}
__device__ __forceinline__ void mbar_wait(uint32_t a) {
    uint32_t done = 0;
    while (!done)
        asm volatile(
            "{ .reg .pred p; mbarrier.try_wait.parity.shared::cta.b64 p, [%1], %2;"
            " selp.b32 %0, 1, 0, p; }"
            : "=r"(done) : "r"(a), "r"(0) : "memory");
}
// one-instruction 32KB tile copy: global (contiguous, pre-swizzled) -> smem
__device__ __forceinline__ void bulk_g2s(uint32_t dst, const void* src,
                                         uint32_t bytes, uint32_t mbar) {
    asm volatile(
        "cp.async.bulk.shared::cta.global.mbarrier::complete_tx::bytes "
        "[%0], [%1], %2, [%3];"
        :: "r"(dst), "l"(src), "r"(bytes), "r"(mbar) : "memory");
}

// full-K (8 t-steps) mma over resident sA + one sB buffer (swizzled layout)
__device__ __forceinline__ void mma_tile(float acc[2][8][4],
                                         uint32_t abase0, uint32_t abase1,
                                         const uint32_t* bbase, uint32_t bbuf,
                                         int c0a, int c0b, int lr) {
    #pragma unroll
    for (int t = 0; t < 8; t++) {
        uint32_t ca = (uint32_t)((((t << 1) | c0a) ^ lr) << 4);
        uint32_t cb = (uint32_t)((((t << 1) | c0b) ^ lr) << 4);
        uint32_t afr[2][4];
        ldsm4(afr[0], abase0 + ca);
        ldsm4(afr[1], abase1 + ca);
        uint32_t bf[16];
        #pragma unroll
        for (int q = 0; q < 4; q++)
            ldsm4(&bf[q * 4], bbuf + bbase[q] + cb);
        #pragma unroll
        for (int mt = 0; mt < 2; mt++)
            #pragma unroll
            for (int nt = 0; nt < 8; nt++)
                mma16816(acc[mt][nt], afr[mt], &bf[nt * 2]);
    }
}

// ---------------------------------------------------------------------------
// kprep: build P pre-swizzled + scaled; compute g_M = ||x'||^2 per row;
// block 0 also builds Ad tables (E, S1).
// ---------------------------------------------------------------------------
__global__ __launch_bounds__(256) void kprep(const float* __restrict__ X) {
    int t = blockIdx.x * 256 + threadIdx.x;
    int row = t >> 3;
    int c   = t & 7;
    const float4* src = reinterpret_cast<const float4*>(
        X + (size_t)row * CC + c * 8);
    float4 v0 = src[0];
    float4 v1 = src[1];

    float xs[8] = {v0.x, v0.y, v0.z, v0.w, v1.x, v1.y, v1.z, v1.w};
    __nv_bfloat16 h[8], l[8];
    float nrm = 0.0f;
    #pragma unroll
    for (int i = 0; i < 8; i++) {
        float x = xs[i] * SQRT_LOG2E;
        nrm += x * x;
        __nv_bfloat16 hh = __float2bfloat16_rn(x);
        h[i] = hh;
        l[i] = __float2bfloat16_rn(x - __bfloat162float(hh));
    }
    // row-norm reduce across the 8 lanes of this row
    nrm += __shfl_xor_sync(0xFFFFFFFFu, nrm, 1);
    nrm += __shfl_xor_sync(0xFFFFFFFFu, nrm, 2);
    nrm += __shfl_xor_sync(0xFFFFFFFFu, nrm, 4);
    if (c == 0) g_M[row] = nrm;

    uint32_t off = (uint32_t)row * 256 + (uint32_t)((c ^ (row & 7)) * 16);
    char* base = reinterpret_cast<char*>(g_P);
    *reinterpret_cast<uint4*>(base + off)       = *reinterpret_cast<uint4*>(h);
    *reinterpret_cast<uint4*>(base + off + 128) = *reinterpret_cast<uint4*>(l);

    if (blockIdx.x == 0 && threadIdx.x < HH) {
        int tt = threadIdx.x;
        d_E[tt] = __expf(-0.5f * (float)(tt * tt));
        float s = 0.0f;
        #pragma unroll 8
        for (int r = 0; r < HH; r++) {
            int d = tt - r;
            s += __expf(-0.5f * (float)(d * d));
        }
        d_S1[tt] = s;
    }
}

// ---------------------------------------------------------------------------
// kA: pass A — 2 column tiles per CTA, all buffers loaded up front, NO
// __syncthreads in the compute path. Per-row partial sums of ex2(v - m).
// ---------------------------------------------------------------------------
__global__ __launch_bounds__(256, 2) void kA() {
    extern __shared__ __nv_bfloat16 smem[];
    __shared__ float sZ[2][128];
    __shared__ alignas(8) uint64_t mbar_s[3];

    const int tid  = threadIdx.x;
    const int lane = tid & 31;
    const int wid  = tid >> 5;
    const int warpM = wid & 3;
    const int warpN = wid >> 2;
    const int g  = lane >> 2;
    const int lr = lane & 7;
    const int r0 = blockIdx.y * 128;
    const int split = blockIdx.x;

    uint32_t s_u = (uint32_t)__cvta_generic_to_shared(smem);
    const uint32_t sa_b = s_u;
    const uint32_t sb_b[2] = { s_u + SB0_OFF, s_u + SB1_OFF };
    uint32_t mb_u = (uint32_t)__cvta_generic_to_shared(mbar_s);

    // LDSM lane row-bases (swizzled layout: row stride 256B)
    const int c0a = lane >> 4;
    const int c0b = (lane >> 3) & 1;
    uint32_t abase0, abase1, bbase[4];
    {
        int rA0 = warpM * 32 + 0  + ((lane >> 3) & 1) * 8 + lr;
        int rA1 = warpM * 32 + 16 + ((lane >> 3) & 1) * 8 + lr;
        abase0 = sa_b + rA0 * 256;
        abase1 = sa_b + rA1 * 256;
        #pragma unroll
        for (int q = 0; q < 4; q++) {
            int n = warpN * 64 + (q * 2 + (lane >> 4)) * 8 + lr;
            bbase[q] = (uint32_t)(n * 256);
        }
    }

    // per-slot fixed shift
    float pm[4];
    #pragma unroll
    for (int s = 0; s < 4; s++) {
        int row = r0 + warpM * 32 + (s >> 1) * 16 + (s & 1) * 8 + g;
        pm[s] = g_M[row];
    }

    if (tid == 0) {
        mbar_init(mb_u, 1);
        mbar_init(mb_u + 8, 1);
        mbar_init(mb_u + 16, 1);
    }
    __syncthreads();

    const char* gp = reinterpret_cast<const char*>(g_P);
    if (tid == 0) {
        mbar_expect(mb_u, TILE_BYTES);
        bulk_g2s(sa_b, gp + (size_t)r0 * 256, TILE_BYTES, mb_u);
        mbar_expect(mb_u + 8, TILE_BYTES);
        bulk_g2s(sb_b[0], gp + (size_t)(split * 256) * 256, TILE_BYTES, mb_u + 8);
        mbar_expect(mb_u + 16, TILE_BYTES);
        bulk_g2s(sb_b[1], gp + (size_t)(split * 256 + 128) * 256, TILE_BYTES, mb_u + 16);
    }
    mbar_wait(mb_u);   // sA ready

    float s_run[4] = {0.0f, 0.0f, 0.0f, 0.0f};

    #pragma unroll
    for (int li = 0; li < 2; li++) {
        mbar_wait(mb_u + (li + 1) * 8);

        float acc[2][8][4];
        #pragma unroll
        for (int mt = 0; mt < 2; mt++)
            #pragma unroll
            for (int nt = 0; nt < 8; nt++)
                #pragma unroll
                for (int i = 0; i < 4; i++)
                    acc[mt][nt][i] = 0.0f;

        mma_tile(acc, abase0, abase1, bbase, sb_b[li], c0a, c0b, lr);

        // fixed-shift partial sums
        #pragma unroll
        for (int s = 0; s < 4; s++) {
            const int mt = s >> 1, h2 = (s & 1) * 2;
            float ssum = 0.0f;
            #pragma unroll
            for (int nt = 0; nt < 8; nt++)
                ssum += ex2f(acc[mt][nt][h2] - pm[s]) +
                        ex2f(acc[mt][nt][h2 + 1] - pm[s]);
            s_run[s] += ssum;
        }
    }

    // sum across the 4 lanes of each quad (same g -> same rows)
    #pragma unroll
    for (int s = 0; s < 4; s++) {
        s_run[s] += __shfl_xor_sync(0xFFFFFFFFu, s_run[s], 1);
        s_run[s] += __shfl_xor_sync(0xFFFFFFFFu, s_run[s], 2);
    }
    if ((lane & 3) == 0) {
        #pragma unroll
        for (int s = 0; s < 4; s++) {
            int rl = warpM * 32 + (s >> 1) * 16 + (s & 1) * 8 + g;
            sZ[warpN][rl] = s_run[s];
        }
    }
    __syncthreads();
    if (tid < 128)
        g_MS[split][r0 + tid] = sZ[0][tid] + sZ[1][tid];
}

// ---------------------------------------------------------------------------
// kms: merge the NSPLIT partial sums -> g_Z
// ---------------------------------------------------------------------------
__global__ __launch_bounds__(256) void kms() {
    int r = blockIdx.x * 256 + threadIdx.x;   // 25 blocks
    float S = 0.0f;
    #pragma unroll
    for (int i = 0; i < NSPLIT; i++) S += g_MS[i][r];
    g_Z[r] = S;
}

// ---------------------------------------------------------------------------
// kB: pass B — same 2-tile structure, fused softmax finalize + threshold,
// streaming stores.
// ---------------------------------------------------------------------------
__global__ __launch_bounds__(256, 2) void kB(float* __restrict__ As) {
    extern __shared__ __nv_bfloat16 smem[];
    __shared__ alignas(8) uint64_t mbar_s[3];

    const int tid  = threadIdx.x;
    const int lane = tid & 31;
    const int wid  = tid >> 5;
    const int warpM = wid & 3;
    const int warpN = wid >> 2;
    const int g  = lane >> 2;
    const int tg = lane & 3;
    const int lr = lane & 7;
    const int r0 = blockIdx.y * 128;
    const int split = blockIdx.x;

    uint32_t s_u = (uint32_t)__cvta_generic_to_shared(smem);
    const uint32_t sa_b = s_u;
    const uint32_t sb_b[2] = { s_u + SB0_OFF, s_u + SB1_OFF };
    uint32_t mb_u = (uint32_t)__cvta_generic_to_shared(mbar_s);

    const int c0a = lane >> 4;
    const int c0b = (lane >> 3) & 1;
    uint32_t abase0, abase1, bbase[4];
    {
        int rA0 = warpM * 32 + 0  + ((lane >> 3) & 1) * 8 + lr;
        int rA1 = warpM * 32 + 16 + ((lane >> 3) & 1) * 8 + lr;
        abase0 = sa_b + rA0 * 256;
        abase1 = sa_b + rA1 * 256;
        #pragma unroll
        for (int q = 0; q < 4; q++) {
            int n = warpN * 64 + (q * 2 + (lane >> 4)) * 8 + lr;
            bbase[q] = (uint32_t)(n * 256);
        }
    }

    if (tid == 0) {
        mbar_init(mb_u, 1);
        mbar_init(mb_u + 8, 1);
        mbar_init(mb_u + 16, 1);
    }
    __syncthreads();

    const char* gp = reinterpret_cast<const char*>(g_P);
    if (tid == 0) {
        mbar_expect(mb_u, TILE_BYTES);
        bulk_g2s(sa_b, gp + (size_t)r0 * 256, TILE_BYTES, mb_u);
        mbar_expect(mb_u + 8, TILE_BYTES);
        bulk_g2s(sb_b[0], gp + (size_t)(split * 256) * 256, TILE_BYTES, mb_u + 8);
        mbar_expect(mb_u + 16, TILE_BYTES);
        bulk_g2s(sb_b[1], gp + (size_t)(split * 256 + 128) * 256, TILE_BYTES, mb_u + 16);
    }

    // per-slot softmax params (overlaps with bulk copies)
    float pm[4], piz[4], pth[4];
    #pragma unroll
    for (int s = 0; s < 4; s++) {
        int row = r0 + warpM * 32 + (s >> 1) * 16 + (s & 1) * 8 + g;
        float Z = g_Z[row];
        pm[s]  = g_M[row];
        piz[s] = 1.0f / Z;
        pth[s] = Z * (1.0f / (float)NN);
    }

    mbar_wait(mb_u);   // sA ready

    #pragma unroll
    for (int li = 0; li < 2; li++) {
        mbar_wait(mb_u + (li + 1) * 8);

        float acc[2][8][4];
        #pragma unroll
        for (int mt = 0; mt < 2; mt++)
            #pragma unroll
            for (int nt = 0; nt < 8; nt++)
                #pragma unroll
                for (int i = 0; i < 4; i++)
                    acc[mt][nt][i] = 0.0f;

        mma_tile(acc, abase0, abase1, bbase, sb_b[li], c0a, c0b, lr);

        // fused softmax epilogue + streaming store for this column tile
        const int c0 = (split * 2 + li) * 128;
        #pragma unroll
        for (int mt = 0; mt < 2; mt++) {
            const int s0 = mt * 2, s1 = mt * 2 + 1;
            #pragma unroll
            for (int nt = 0; nt < 8; nt++) {
                int row = r0 + warpM * 32 + mt * 16 + g;
                int col = c0 + warpN * 64 + nt * 8 + tg * 2;
                float e0 = ex2f(acc[mt][nt][0] - pm[s0]);
                float e1 = ex2f(acc[mt][nt][1] - pm[s0]);
                float e2 = ex2f(acc[mt][nt][2] - pm[s1]);
                float e3 = ex2f(acc[mt][nt][3] - pm[s1]);
                float2 v0, v1;
                v0.x = (e0 < pth[s0]) ? 0.0f : e0 * piz[s0];
                v0.y = (e1 < pth[s0]) ? 0.0f : e1 * piz[s0];
                v1.x = (e2 < pth[s1]) ? 0.0f : e2 * piz[s1];
                v1.y = (e3 < pth[s1]) ? 0.0f : e3 * piz[s1];
                __stcs(reinterpret_cast<float2*>(&As[(size_t)row * NN + col]), v0);
                __stcs(reinterpret_cast<float2*>(&As[(size_t)(row + 8) * NN + col]), v1);
            }
        }
    }
}

// ---------------------------------------------------------------------------
// k3: analytic Ad, one row per CTA via Kronecker of two 80-vectors.
// Launched on a side stream, overlapping kA/kms/kB.
// ---------------------------------------------------------------------------
__global__ __launch_bounds__(256) void k3_ad(float* __restrict__ Ad) {
    __shared__ float erinv[HH];
    __shared__ float4 ec4[HH / 4];

    const int tid = threadIdx.x;
    const int i   = blockIdx.x;
    const int ri  = i / HH;
    const int ci  = i - ri * HH;

    const float inv = 1.0f / (__ldg(&d_S1[ri]) * __ldg(&d_S1[ci]) - 1.0f);
    if (tid < HH) {
        int dr = ri - tid; dr = dr < 0 ? -dr : dr;
        int dc = ci - tid; dc = dc < 0 ? -dc : dc;
        erinv[tid] = __ldg(&d_E[dr]) * inv;
        reinterpret_cast<float*>(ec4)[tid] = __ldg(&d_E[dc]);
    }
    __syncthreads();

    float* rowp = Ad + (size_t)i * NN;
    for (int q = tid; q < NN / 4; q += 256) {
        int rj = q / 20;          // 20 float4 per 80-col block
        int cq = q - rj * 20;
        float er = erinv[rj];
        float4 e = ec4[cq];
        float4 o;
        o.x = er * e.x;
        o.y = er * e.y;
        o.z = er * e.z;
        o.w = er * e.w;
        __stcs(reinterpret_cast<float4*>(rowp) + q, o);
    }
    __syncthreads();
    if (tid == 0) rowp[i] = 0.0f;
}

// ---------------------------------------------------------------------------
extern "C" void kernel_launch(void* const* d_in, const int* in_sizes, int n_in,
                              void* d_out, int out_size) {
    const float* X = (const float*)d_in[0];
    float* Ad = (float*)d_out;                       // first N*N floats
    float* As = (float*)d_out + (size_t)NN * NN;     // second N*N floats

    static cudaStream_t s_side = nullptr;
    static cudaEvent_t ev_fork = nullptr, ev_join = nullptr;
    if (!s_side) {
        cudaStreamCreateWithFlags(&s_side, cudaStreamNonBlocking);
        cudaEventCreateWithFlags(&ev_fork, cudaEventDisableTiming);
        cudaEventCreateWithFlags(&ev_join, cudaEventDisableTiming);
        cudaFuncSetAttribute(kA, cudaFuncAttributeMaxDynamicSharedMemorySize, SMEM_BYTES);
        cudaFuncSetAttribute(kB, cudaFuncAttributeMaxDynamicSharedMemorySize, SMEM_BYTES);
    }

    kprep<<<200, 256>>>(X);

    // fork: k3_ad runs on the side stream, overlapping kA/kms/kB
    cudaEventRecord(ev_fork, 0);
    cudaStreamWaitEvent(s_side, ev_fork, 0);
    k3_ad<<<NN, 256, 0, s_side>>>(Ad);
    cudaEventRecord(ev_join, s_side);

    kA<<<dim3(NSPLIT, NN / 128), 256, SMEM_BYTES>>>();
    kms<<<NN / 256, 256>>>();
    kB<<<dim3(NSPLIT, NN / 128), 256, SMEM_BYTES>>>(As);

    // join
    cudaStreamWaitEvent(0, ev_join, 0);
}